// round 14
// baseline (speedup 1.0000x reference)
#include <cuda_runtime.h>
#include <cuda_bf16.h>
#include <math.h>
#include <stdint.h>

// Problem constants
#define T_    512
#define B_    64
#define H_    1024
#define C_    32000
#define SIXH  6144
#define M_    (T_*B_)
#define BH    (B_*H_)
#define YSIZE (B_*C_)
#define GRID_G 128
#define NSTEP 1022

// -------- scratch --------
__device__ float    g_xin[M_*H_];
__device__ float    g_part2[2][8*BH];
__device__ __nv_bfloat16 g_hh[2][BH];
__device__ __nv_bfloat16 g_hl[2][BH];
__device__ __nv_bfloat16 g_xe_hi[M_*H_];
__device__ __nv_bfloat16 g_xe_lo[M_*H_];
__device__ __nv_bfloat16 g_wx_hi[H_*H_];
__device__ __nv_bfloat16 g_wx_lo[H_*H_];
__device__ unsigned g_pairc[8];    // 256 warp-arrivals per step
__device__ unsigned g_famc[8];     // 256 warp-arrivals per step
__device__ unsigned g_epoch = 0;

__device__ __forceinline__ void arrive_cnt(unsigned* c) {
    asm volatile("red.release.gpu.global.add.u32 [%0], %1;" :: "l"(c), "r"(1u) : "memory");
}
__device__ __forceinline__ void wait_cnt(unsigned* c, unsigned target) {
    unsigned v;
    do { asm volatile("ld.acquire.gpu.global.u32 %0, [%1];" : "=r"(v) : "l"(c) : "memory"); }
    while (v < target);
}

__device__ __forceinline__ uint32_t smem_u32(const void* p) {
    uint32_t a;
    asm("{ .reg .u64 t; cvta.to.shared.u64 t, %1; cvt.u32.u64 %0, t; }" : "=r"(a) : "l"(p));
    return a;
}
__device__ __forceinline__ void ldsm4(uint32_t* r, uint32_t a) {
    asm volatile("ldmatrix.sync.aligned.m8n8.x4.shared.b16 {%0,%1,%2,%3}, [%4];"
        : "=r"(r[0]), "=r"(r[1]), "=r"(r[2]), "=r"(r[3]) : "r"(a));
}
__device__ __forceinline__ void mma_bf16(float* d, const uint32_t* a, const uint32_t* b) {
    asm volatile("mma.sync.aligned.m16n8k16.row.col.f32.bf16.bf16.f32 "
        "{%0,%1,%2,%3}, {%4,%5,%6,%7}, {%8,%9}, {%0,%1,%2,%3};"
        : "+f"(d[0]), "+f"(d[1]), "+f"(d[2]), "+f"(d[3])
        : "r"(a[0]), "r"(a[1]), "r"(a[2]), "r"(a[3]), "r"(b[0]), "r"(b[1]));
}
__device__ __forceinline__ void split_bf16(float v, __nv_bfloat16& hi, __nv_bfloat16& lo) {
    hi = __float2bfloat16(v);
    lo = __float2bfloat16(v - __bfloat162float(hi));
}

// ================= Prepass A: xe = emb[x] -> bf16 hi/lo =================
__global__ void conv_xe_kernel(const int* __restrict__ x, const float* __restrict__ emb) {
    const int tid = threadIdx.x;
    #pragma unroll
    for (int it = 0; it < 8; it++) {
        int r = blockIdx.x * 8 + it;
        int token = __ldg(&x[r]);
        float4 v = *(const float4*)&emb[(size_t)token * H_ + tid * 4];
        __nv_bfloat16 hx, lx, hy, ly, hz, lz, hw, lw;
        split_bf16(v.x, hx, lx); split_bf16(v.y, hy, ly);
        split_bf16(v.z, hz, lz); split_bf16(v.w, hw, lw);
        size_t o = (size_t)r * H_ + tid * 4;
        *(__nv_bfloat162*)&g_xe_hi[o]     = __halves2bfloat162(hx, hy);
        *(__nv_bfloat162*)&g_xe_hi[o + 2] = __halves2bfloat162(hz, hw);
        *(__nv_bfloat162*)&g_xe_lo[o]     = __halves2bfloat162(lx, ly);
        *(__nv_bfloat162*)&g_xe_lo[o + 2] = __halves2bfloat162(lz, lw);
    }
}

// ================= Prepass B: Wx -> bf16 hi/lo transposed [n][k] =================
__global__ void conv_wx_kernel(const float* __restrict__ w1) {
    const int n = blockIdx.x;
    for (int k = threadIdx.x; k < H_; k += 256) {
        float v = w1[(size_t)k * SIXH + n];
        __nv_bfloat16 hi, lo;
        split_bf16(v, hi, lo);
        g_wx_hi[n * H_ + k] = hi;
        g_wx_lo[n * H_ + k] = lo;
    }
}

// ================= Kernel 1: xin = xe @ Wx + b (round-13 proven, unchanged) ==========
#define XSTR 144
#define SA_HI 0
#define SA_LO (128*XSTR)
#define SB_HI (2*128*XSTR)
#define SB_LO (3*128*XSTR)
#define XS_TOTAL (4*128*XSTR)
__global__ void __launch_bounds__(256, 2)
xin_mma_kernel(const float* __restrict__ b1) {
    extern __shared__ __align__(16) char smem[];
    const uint32_t sb = smem_u32(smem);
    const int tid = threadIdx.x;
    const int wid = tid >> 5, l = tid & 31;
    const int mw = wid & 3, nw = wid >> 2;
    const int n0 = blockIdx.x * 128;
    const int r0 = blockIdx.y * 128;

    const uint32_t a_row = (uint32_t)(mw*32 + (l & 7) + ((l >> 3) & 1) * 8);
    const uint32_t a_off = a_row * XSTR + ((l >> 4) & 1) * 16;
    const uint32_t b_off = (uint32_t)((nw*64 + (l & 7) + ((l >> 4) & 1) * 8) * XSTR
                                      + ((l >> 3) & 1) * 16);

    float d[2][8][4] = {};
    for (int kc = 0; kc < 16; kc++) {
        __syncthreads();
        #pragma unroll
        for (int it = 0; it < 4; it++) {
            int f = tid + it * 256;
            int r = f >> 3, q = f & 7;
            size_t ga = (size_t)(r0 + r) * H_ + kc*64 + q*8;
            size_t gb = (size_t)(n0 + r) * H_ + kc*64 + q*8;
            *(uint4*)(smem + SA_HI + r*XSTR + q*16) = *(const uint4*)&g_xe_hi[ga];
            *(uint4*)(smem + SA_LO + r*XSTR + q*16) = *(const uint4*)&g_xe_lo[ga];
            *(uint4*)(smem + SB_HI + r*XSTR + q*16) = *(const uint4*)&g_wx_hi[gb];
            *(uint4*)(smem + SB_LO + r*XSTR + q*16) = *(const uint4*)&g_wx_lo[gb];
        }
        __syncthreads();
        #pragma unroll
        for (int s = 0; s < 4; s++) {
            uint32_t ahi[2][4], alo[2][4];
            #pragma unroll
            for (int i = 0; i < 2; i++) {
                uint32_t ao = a_off + (uint32_t)(i * 16 * XSTR) + s * 32;
                ldsm4(ahi[i], sb + SA_HI + ao);
                ldsm4(alo[i], sb + SA_LO + ao);
            }
            #pragma unroll
            for (int np = 0; np < 4; np++) {
                uint32_t bhi[4], blo[4];
                uint32_t bo = b_off + (uint32_t)(np * 16 * XSTR) + s * 32;
                ldsm4(bhi, sb + SB_HI + bo);
                ldsm4(blo, sb + SB_LO + bo);
                #pragma unroll
                for (int h = 0; h < 2; h++) {
                    int ns = np*2 + h;
                    #pragma unroll
                    for (int i = 0; i < 2; i++) {
                        mma_bf16(d[i][ns], ahi[i], bhi + h*2);
                        mma_bf16(d[i][ns], ahi[i], blo + h*2);
                        mma_bf16(d[i][ns], alo[i], bhi + h*2);
                    }
                }
            }
        }
    }
    #pragma unroll
    for (int i = 0; i < 2; i++) {
        int row = r0 + mw*32 + i*16 + (l >> 2);
        #pragma unroll
        for (int ns = 0; ns < 8; ns++) {
            int col = n0 + nw*64 + ns*8 + (l & 3) * 2;
            float2 bb = *(const float2*)&b1[col];
            *(float2*)&g_xin[(size_t)row * H_ + col] =
                make_float2(d[i][ns][0] + bb.x, d[i][ns][1] + bb.y);
            *(float2*)&g_xin[(size_t)(row + 8) * H_ + col] =
                make_float2(d[i][ns][2] + bb.x, d[i][ns][3] + bb.y);
        }
    }
}

// ================= Kernel 2: persistent recurrence — per-warp arrivals ==========
// Per step: 3 CTA barriers (famc fan-out, stage->GEMM, pairc fan-out); arrivals per-warp.
#define RSTR   272
#define S_AHI  0
#define S_ALO  (64*RSTR)
#define S_BHI  (2*64*RSTR)
#define S_BLO  (3*64*RSTR)
#define S_TOTAL (4*64*RSTR)

__global__ void __launch_bounds__(512, 1)
recur_kernel(const float* __restrict__ w1, float* __restrict__ out_hist) {
    extern __shared__ __align__(1024) char smem[];
    const uint32_t sb = smem_u32(smem);
    const int tid = threadIdx.x;
    const int wid = tid >> 5;
    const int l   = tid & 31;
    const int bx  = blockIdx.x;
    const int nt = bx >> 3, ks = bx & 7;
    const int m  = wid & 3;
    const int nh = wid >> 2;

    const unsigned E = __ldcg(&g_epoch);

    // stage Wh slab -> Bhi/Blo[n][k] bf16 in smem (once)
    #pragma unroll
    for (int it = 0; it < 4; it++) {
        int f = tid + it * 512;
        int k = f >> 4, nq = (f & 15) * 4;
        float4 v = *(const float4*)&w1[(ks*128 + k) * SIXH + H_ + nt*64 + nq];
        float vv[4] = {v.x, v.y, v.z, v.w};
        #pragma unroll
        for (int q = 0; q < 4; q++) {
            int off = (nq + q) * RSTR + k * 2;
            __nv_bfloat16 hi, lo;
            split_bf16(vv[q], hi, lo);
            *(__nv_bfloat16*)(smem + S_BHI + off) = hi;
            *(__nv_bfloat16*)(smem + S_BLO + off) = lo;
        }
    }

    // reduce-chunk coords: 512 threads x 1 float
    const int b_r = nt*4 + (tid >> 7);
    const int n_r = ks*128 + (tid & 127);

    // prologue (s=0): h0 = tanh(xin[0]); per-warp arrivals
    {
        float xv = g_xin[b_r * H_ + n_r];
        float v = tanhf(xv);
        __nv_bfloat16 hi, lo;
        split_bf16(v, hi, lo);
        g_hh[0][b_r * H_ + n_r] = hi;
        g_hl[0][b_r * H_ + n_r] = lo;
        out_hist[(size_t)b_r * (T_*H_) + n_r] = v;
    }
    __syncwarp();
    if (l == 0) { arrive_cnt(&g_famc[ks]); arrive_cnt(&g_pairc[nt >> 1]); }
    __syncthreads();   // Wh smem visible before B-frag hoist

    // ldmatrix bases
    const uint32_t a_addr0 = sb + (uint32_t)((m*16 + (l & 7) + ((l >> 3) & 1) * 8) * RSTR
                                             + ((l >> 4) & 1) * 16);
    const uint32_t b_addr0 = sb + (uint32_t)((nh*16 + (l & 7) + ((l >> 4) & 1) * 8) * RSTR
                                             + ((l >> 3) & 1) * 16);

    // hoist ALL B fragments to registers (constant for all steps)
    uint32_t bh[8][4], bl[8][4];
    #pragma unroll
    for (int ss = 0; ss < 8; ss++) {
        ldsm4(bh[ss], b_addr0 + S_BHI + ss * 32);
        ldsm4(bl[ss], b_addr0 + S_BLO + ss * 32);
    }

    for (int s = 1; s <= NSTEP; s++) {
        // prefetch xin for this step's reduce
        const int t = (s + 1) >> 1;
        float xp = __ldcg(&g_xin[(size_t)t * BH + b_r * H_ + n_r]);

        // ---- wait h_{s-1} from family ks (tid0 polls; 256 warp-arrivals) ----
        if (tid == 0) wait_cnt(&g_famc[ks], (E + (unsigned)s) * 256u);
        __syncthreads();                                   // S1: fan-out
        {
            const __nv_bfloat16* hsrc_h = g_hh[(s-1) & 1];
            const __nv_bfloat16* hsrc_l = g_hl[(s-1) & 1];
            #pragma unroll
            for (int it = 0; it < 4; it++) {
                int f = tid + it * 512;
                int buf = f >> 10, g = f & 1023;
                int row = g >> 4, q = g & 15;
                const __nv_bfloat16* src = (buf ? hsrc_l : hsrc_h) + row * H_ + ks*128 + q*8;
                char* dst = smem + (buf ? S_ALO : S_AHI) + row * RSTR + q * 16;
                *(uint4*)dst = __ldcg((const uint4*)src);
            }
        }
        __syncthreads();                                   // S2: stage -> GEMM

        // ---- GEMM: split accumulator chains ----
        float dhh[2][4] = {}, dml[2][4] = {};
        #pragma unroll
        for (int ss = 0; ss < 8; ss++) {
            uint32_t a_hi[4], a_lo[4];
            ldsm4(a_hi, a_addr0 + S_AHI + ss * 32);
            ldsm4(a_lo, a_addr0 + S_ALO + ss * 32);
            mma_bf16(dhh[0], a_hi, bh[ss] + 0);
            mma_bf16(dhh[1], a_hi, bh[ss] + 2);
            mma_bf16(dml[0], a_hi, bl[ss] + 0);
            mma_bf16(dml[1], a_hi, bl[ss] + 2);
            mma_bf16(dml[0], a_lo, bh[ss] + 0);
            mma_bf16(dml[1], a_lo, bh[ss] + 2);
        }
        {
            float* pb = g_part2[s & 1];
            int row0 = m*16 + (l >> 2);
            int gcol = nt*64 + nh*16 + (l & 3) * 2;
            float* p = &pb[ks*BH + row0*H_ + gcol];
            #pragma unroll
            for (int ns = 0; ns < 2; ns++) {
                *(float2*)(p + ns*8) =
                    make_float2(dhh[ns][0] + dml[ns][0], dhh[ns][1] + dml[ns][1]);
                *(float2*)(p + ns*8 + 8*H_) =
                    make_float2(dhh[ns][2] + dml[ns][2], dhh[ns][3] + dml[ns][3]);
            }
        }
        __syncwarp();                                      // warp's stores ordered
        if (l == 0) arrive_cnt(&g_pairc[nt >> 1]);         // per-warp arrival

        // ---- wait parts from nts {2ks,2ks+1} ----
        if (tid == 0) wait_cnt(&g_pairc[ks], (E + (unsigned)s + 1u) * 256u);
        __syncthreads();                                   // S4: fan-out
        {
            const float* pb = g_part2[s & 1];
            float acc = xp;
            #pragma unroll
            for (int p = 0; p < 8; p++)
                acc += __ldcg(&pb[p*BH + b_r*H_ + n_r]);
            float v = tanhf(acc);
            __nv_bfloat16 hi, lo;
            split_bf16(v, hi, lo);
            g_hh[s & 1][b_r * H_ + n_r] = hi;
            g_hl[s & 1][b_r * H_ + n_r] = lo;
            __syncwarp();                                  // warp's h stores ordered
            if (l == 0) arrive_cnt(&g_famc[ks]);           // per-warp arrival
            if ((s & 1) == 0)                              // off the critical path
                out_hist[(size_t)b_r * (T_*H_) + t * H_ + n_r] = v;
        }
    }
    if (bx == 0 && tid == 0) g_epoch = E + (unsigned)(NSTEP + 1);
}

// ================= Kernel 3: fc — fc_w converted inline (prepass removed) ==========
#define FSTR 144
#define FA_HI 0
#define FA_LO (64*FSTR)
#define FB_HI (2*64*FSTR)
#define FB_LO (FB_HI + 256*FSTR)
#define FS_TOTAL (FB_LO + 256*FSTR)
__global__ void __launch_bounds__(256, 1)
fc_mma_kernel(const float* __restrict__ fc_w, const float* __restrict__ fc_b,
              float* __restrict__ y) {
    extern __shared__ __align__(16) char smem[];
    const uint32_t sb = smem_u32(smem);
    const int tid = threadIdx.x;
    const int wid = tid >> 5, l = tid & 31;
    const int mw = wid & 1, nw = wid >> 1;
    const int c0 = blockIdx.x * 256;

    const uint32_t a_off = (uint32_t)((mw*32 + (l & 7) + ((l >> 3) & 1) * 8) * FSTR
                                      + ((l >> 4) & 1) * 16);
    const uint32_t b_off = (uint32_t)((nw*64 + (l & 7) + ((l >> 4) & 1) * 8) * FSTR
                                      + ((l >> 3) & 1) * 16);

    float d[2][8][4] = {};
    for (int kc = 0; kc < 16; kc++) {
        __syncthreads();
        // stage A: 64x64 hi+lo from g_hh/g_hl[0]
        #pragma unroll
        for (int it = 0; it < 4; it++) {
            int f = tid + it * 256;
            int buf = f >> 9, g = f & 511;
            int row = g >> 3, q = g & 7;
            const __nv_bfloat16* src = (buf ? g_hl[0] : g_hh[0]) + row * H_ + kc*64 + q*8;
            *(uint4*)(smem + (buf ? FA_LO : FA_HI) + row*FSTR + q*16) = *(const uint4*)src;
        }
        // stage B: 256 rows x 64 k from fp32 fc_w, split inline (DRAM-latency hides ALU)
        #pragma unroll
        for (int it = 0; it < 16; it++) {
            int f = tid + it * 256;            // 4096 float4 tasks: row(256) x q4(16)
            int row = f >> 4, q4 = f & 15;
            float4 v = *(const float4*)&fc_w[(size_t)(c0 + row) * H_ + kc*64 + q4*4];
            __nv_bfloat16 hx, lx, hy, ly, hz, lz, hw, lw;
            split_bf16(v.x, hx, lx); split_bf16(v.y, hy, ly);
            split_bf16(v.z, hz, lz); split_bf16(v.w, hw, lw);
            uint32_t ho = (uint32_t)(row*FSTR + q4*8);
            *(__nv_bfloat162*)(smem + FB_HI + ho)     = __halves2bfloat162(hx, hy);
            *(__nv_bfloat162*)(smem + FB_HI + ho + 4) = __halves2bfloat162(hz, hw);
            *(__nv_bfloat162*)(smem + FB_LO + ho)     = __halves2bfloat162(lx, ly);
            *(__nv_bfloat162*)(smem + FB_LO + ho + 4) = __halves2bfloat162(lz, lw);
        }
        __syncthreads();
        #pragma unroll
        for (int s = 0; s < 4; s++) {
            uint32_t ahi[2][4], alo[2][4];
            #pragma unroll
            for (int i = 0; i < 2; i++) {
                uint32_t ao = a_off + (uint32_t)(i * 16 * FSTR) + s * 32;
                ldsm4(ahi[i], sb + FA_HI + ao);
                ldsm4(alo[i], sb + FA_LO + ao);
            }
            #pragma unroll
            for (int np = 0; np < 4; np++) {
                uint32_t bhi[4], blo[4];
                uint32_t bo = b_off + (uint32_t)(np * 16 * FSTR) + s * 32;
                ldsm4(bhi, sb + FB_HI + bo);
                ldsm4(blo, sb + FB_LO + bo);
                #pragma unroll
                for (int h = 0; h < 2; h++) {
                    int ns = np*2 + h;
                    #pragma unroll
                    for (int i = 0; i < 2; i++) {
                        mma_bf16(d[i][ns], ahi[i], bhi + h*2);
                        mma_bf16(d[i][ns], ahi[i], blo + h*2);
                        mma_bf16(d[i][ns], alo[i], bhi + h*2);
                    }
                }
            }
        }
    }
    #pragma unroll
    for (int i = 0; i < 2; i++) {
        int row = mw*32 + i*16 + (l >> 2);
        #pragma unroll
        for (int ns = 0; ns < 8; ns++) {
            int col = c0 + nw*64 + ns*8 + (l & 3) * 2;
            float2 bb = *(const float2*)&fc_b[col];
            *(float2*)&y[(size_t)row * C_ + col] =
                make_float2(d[i][ns][0] + bb.x, d[i][ns][1] + bb.y);
            *(float2*)&y[(size_t)(row + 8) * C_ + col] =
                make_float2(d[i][ns][2] + bb.x, d[i][ns][3] + bb.y);
        }
    }
}

// ================= launch =================
extern "C" void kernel_launch(void* const* d_in, const int* in_sizes, int n_in,
                              void* d_out, int out_size) {
    const int*   x    = (const int*)  d_in[0];
    const float* emb  = (const float*)d_in[1];
    const float* w1   = (const float*)d_in[2];
    const float* b1   = (const float*)d_in[3];
    const float* fc_w = (const float*)d_in[4];
    const float* fc_b = (const float*)d_in[5];
    float* out = (float*)d_out;

    conv_wx_kernel<<<H_, 256>>>(w1);
    conv_xe_kernel<<<M_/8, 256>>>(x, emb);

    dim3 gx(H_/128, M_/128);
    cudaFuncSetAttribute(xin_mma_kernel, cudaFuncAttributeMaxDynamicSharedMemorySize, XS_TOTAL);
    xin_mma_kernel<<<gx, 256, XS_TOTAL>>>(b1);

    cudaFuncSetAttribute(recur_kernel, cudaFuncAttributeMaxDynamicSharedMemorySize, S_TOTAL);
    recur_kernel<<<GRID_G, 512, S_TOTAL>>>(w1, out + YSIZE);

    cudaFuncSetAttribute(fc_mma_kernel, cudaFuncAttributeMaxDynamicSharedMemorySize, FS_TOTAL);
    fc_mma_kernel<<<C_/256, 256, FS_TOTAL>>>(fc_w, fc_b, out);
}

// round 15
// speedup vs baseline: 1.4058x; 1.4058x over previous
#include <cuda_runtime.h>
#include <cuda_bf16.h>
#include <math.h>
#include <stdint.h>

// Problem constants
#define T_    512
#define B_    64
#define H_    1024
#define C_    32000
#define SIXH  6144
#define M_    (T_*B_)
#define BH    (B_*H_)
#define YSIZE (B_*C_)
#define GRID_G 128
#define NSTEP 1022

// -------- scratch --------
__device__ float    g_xin[M_*H_];
__device__ float    g_part2[2][8*BH];
__device__ __nv_bfloat16 g_hh[2][BH];
__device__ __nv_bfloat16 g_hl[2][BH];
__device__ __nv_bfloat16 g_xe_hi[M_*H_];
__device__ __nv_bfloat16 g_xe_lo[M_*H_];
__device__ __nv_bfloat16 g_wx_hi[H_*H_];
__device__ __nv_bfloat16 g_wx_lo[H_*H_];
__device__ unsigned g_pairc[8];    // 16 CTA arrivals per step (tid0 only)
__device__ unsigned g_famc[8];     // 16 CTA arrivals per step (tid0 only)
__device__ unsigned g_epoch = 0;

__device__ __forceinline__ void arrive_cnt(unsigned* c) {
    asm volatile("red.release.gpu.global.add.u32 [%0], %1;" :: "l"(c), "r"(1u) : "memory");
}
__device__ __forceinline__ void wait_cnt(unsigned* c, unsigned target) {
    unsigned v;
    do { asm volatile("ld.acquire.gpu.global.u32 %0, [%1];" : "=r"(v) : "l"(c) : "memory"); }
    while (v < target);
}

__device__ __forceinline__ uint32_t smem_u32(const void* p) {
    uint32_t a;
    asm("{ .reg .u64 t; cvta.to.shared.u64 t, %1; cvt.u32.u64 %0, t; }" : "=r"(a) : "l"(p));
    return a;
}
__device__ __forceinline__ void ldsm4(uint32_t* r, uint32_t a) {
    asm volatile("ldmatrix.sync.aligned.m8n8.x4.shared.b16 {%0,%1,%2,%3}, [%4];"
        : "=r"(r[0]), "=r"(r[1]), "=r"(r[2]), "=r"(r[3]) : "r"(a));
}
__device__ __forceinline__ void mma_bf16(float* d, const uint32_t* a, const uint32_t* b) {
    asm volatile("mma.sync.aligned.m16n8k16.row.col.f32.bf16.bf16.f32 "
        "{%0,%1,%2,%3}, {%4,%5,%6,%7}, {%8,%9}, {%0,%1,%2,%3};"
        : "+f"(d[0]), "+f"(d[1]), "+f"(d[2]), "+f"(d[3])
        : "r"(a[0]), "r"(a[1]), "r"(a[2]), "r"(a[3]), "r"(b[0]), "r"(b[1]));
}
__device__ __forceinline__ void split_bf16(float v, __nv_bfloat16& hi, __nv_bfloat16& lo) {
    hi = __float2bfloat16(v);
    lo = __float2bfloat16(v - __bfloat162float(hi));
}

// ================= Prepass A: xe = emb[x] -> bf16 hi/lo =================
__global__ void conv_xe_kernel(const int* __restrict__ x, const float* __restrict__ emb) {
    const int tid = threadIdx.x;
    #pragma unroll
    for (int it = 0; it < 8; it++) {
        int r = blockIdx.x * 8 + it;
        int token = __ldg(&x[r]);
        float4 v = *(const float4*)&emb[(size_t)token * H_ + tid * 4];
        __nv_bfloat16 hx, lx, hy, ly, hz, lz, hw, lw;
        split_bf16(v.x, hx, lx); split_bf16(v.y, hy, ly);
        split_bf16(v.z, hz, lz); split_bf16(v.w, hw, lw);
        size_t o = (size_t)r * H_ + tid * 4;
        *(__nv_bfloat162*)&g_xe_hi[o]     = __halves2bfloat162(hx, hy);
        *(__nv_bfloat162*)&g_xe_hi[o + 2] = __halves2bfloat162(hz, hw);
        *(__nv_bfloat162*)&g_xe_lo[o]     = __halves2bfloat162(lx, ly);
        *(__nv_bfloat162*)&g_xe_lo[o + 2] = __halves2bfloat162(lz, lw);
    }
}

// ================= Prepass B: Wx -> bf16 hi/lo transposed [n][k] =================
__global__ void conv_wx_kernel(const float* __restrict__ w1) {
    const int n = blockIdx.x;
    for (int k = threadIdx.x; k < H_; k += 256) {
        float v = w1[(size_t)k * SIXH + n];
        __nv_bfloat16 hi, lo;
        split_bf16(v, hi, lo);
        g_wx_hi[n * H_ + k] = hi;
        g_wx_lo[n * H_ + k] = lo;
    }
}

// ================= Kernel 1: xin = xe @ Wx + b (round-13 proven, unchanged) ==========
#define XSTR 144
#define SA_HI 0
#define SA_LO (128*XSTR)
#define SB_HI (2*128*XSTR)
#define SB_LO (3*128*XSTR)
#define XS_TOTAL (4*128*XSTR)
__global__ void __launch_bounds__(256, 2)
xin_mma_kernel(const float* __restrict__ b1) {
    extern __shared__ __align__(16) char smem[];
    const uint32_t sb = smem_u32(smem);
    const int tid = threadIdx.x;
    const int wid = tid >> 5, l = tid & 31;
    const int mw = wid & 3, nw = wid >> 2;
    const int n0 = blockIdx.x * 128;
    const int r0 = blockIdx.y * 128;

    const uint32_t a_row = (uint32_t)(mw*32 + (l & 7) + ((l >> 3) & 1) * 8);
    const uint32_t a_off = a_row * XSTR + ((l >> 4) & 1) * 16;
    const uint32_t b_off = (uint32_t)((nw*64 + (l & 7) + ((l >> 4) & 1) * 8) * XSTR
                                      + ((l >> 3) & 1) * 16);

    float d[2][8][4] = {};
    for (int kc = 0; kc < 16; kc++) {
        __syncthreads();
        #pragma unroll
        for (int it = 0; it < 4; it++) {
            int f = tid + it * 256;
            int r = f >> 3, q = f & 7;
            size_t ga = (size_t)(r0 + r) * H_ + kc*64 + q*8;
            size_t gb = (size_t)(n0 + r) * H_ + kc*64 + q*8;
            *(uint4*)(smem + SA_HI + r*XSTR + q*16) = *(const uint4*)&g_xe_hi[ga];
            *(uint4*)(smem + SA_LO + r*XSTR + q*16) = *(const uint4*)&g_xe_lo[ga];
            *(uint4*)(smem + SB_HI + r*XSTR + q*16) = *(const uint4*)&g_wx_hi[gb];
            *(uint4*)(smem + SB_LO + r*XSTR + q*16) = *(const uint4*)&g_wx_lo[gb];
        }
        __syncthreads();
        #pragma unroll
        for (int s = 0; s < 4; s++) {
            uint32_t ahi[2][4], alo[2][4];
            #pragma unroll
            for (int i = 0; i < 2; i++) {
                uint32_t ao = a_off + (uint32_t)(i * 16 * XSTR) + s * 32;
                ldsm4(ahi[i], sb + SA_HI + ao);
                ldsm4(alo[i], sb + SA_LO + ao);
            }
            #pragma unroll
            for (int np = 0; np < 4; np++) {
                uint32_t bhi[4], blo[4];
                uint32_t bo = b_off + (uint32_t)(np * 16 * XSTR) + s * 32;
                ldsm4(bhi, sb + SB_HI + bo);
                ldsm4(blo, sb + SB_LO + bo);
                #pragma unroll
                for (int h = 0; h < 2; h++) {
                    int ns = np*2 + h;
                    #pragma unroll
                    for (int i = 0; i < 2; i++) {
                        mma_bf16(d[i][ns], ahi[i], bhi + h*2);
                        mma_bf16(d[i][ns], ahi[i], blo + h*2);
                        mma_bf16(d[i][ns], alo[i], bhi + h*2);
                    }
                }
            }
        }
    }
    #pragma unroll
    for (int i = 0; i < 2; i++) {
        int row = r0 + mw*32 + i*16 + (l >> 2);
        #pragma unroll
        for (int ns = 0; ns < 8; ns++) {
            int col = n0 + nw*64 + ns*8 + (l & 3) * 2;
            float2 bb = *(const float2*)&b1[col];
            *(float2*)&g_xin[(size_t)row * H_ + col] =
                make_float2(d[i][ns][0] + bb.x, d[i][ns][1] + bb.y);
            *(float2*)&g_xin[(size_t)(row + 8) * H_ + col] =
                make_float2(d[i][ns][2] + bb.x, d[i][ns][3] + bb.y);
        }
    }
}

// ================= Kernel 2: persistent recurrence (round-13 exact) ==========
#define RSTR   272
#define S_AHI  0
#define S_ALO  (64*RSTR)
#define S_BHI  (2*64*RSTR)
#define S_BLO  (3*64*RSTR)
#define S_TOTAL (4*64*RSTR)

__global__ void __launch_bounds__(512, 1)
recur_kernel(const float* __restrict__ w1, float* __restrict__ out_hist) {
    extern __shared__ __align__(1024) char smem[];
    const uint32_t sb = smem_u32(smem);
    const int tid = threadIdx.x;
    const int wid = tid >> 5;
    const int l   = tid & 31;
    const int bx  = blockIdx.x;
    const int nt = bx >> 3, ks = bx & 7;
    const int m  = wid & 3;
    const int nh = wid >> 2;

    const unsigned E = __ldcg(&g_epoch);

    // stage Wh slab -> Bhi/Blo[n][k] bf16 in smem (once)
    #pragma unroll
    for (int it = 0; it < 4; it++) {
        int f = tid + it * 512;
        int k = f >> 4, nq = (f & 15) * 4;
        float4 v = *(const float4*)&w1[(ks*128 + k) * SIXH + H_ + nt*64 + nq];
        float vv[4] = {v.x, v.y, v.z, v.w};
        #pragma unroll
        for (int q = 0; q < 4; q++) {
            int off = (nq + q) * RSTR + k * 2;
            __nv_bfloat16 hi, lo;
            split_bf16(vv[q], hi, lo);
            *(__nv_bfloat16*)(smem + S_BHI + off) = hi;
            *(__nv_bfloat16*)(smem + S_BLO + off) = lo;
        }
    }

    // reduce-chunk coords: 512 threads x 1 float
    const int b_r = nt*4 + (tid >> 7);
    const int n_r = ks*128 + (tid & 127);

    // prologue (s=0): h0 = tanh(xin[0])
    {
        float xv = g_xin[b_r * H_ + n_r];
        float v = tanhf(xv);
        __nv_bfloat16 hi, lo;
        split_bf16(v, hi, lo);
        g_hh[0][b_r * H_ + n_r] = hi;
        g_hl[0][b_r * H_ + n_r] = lo;
        out_hist[(size_t)b_r * (T_*H_) + n_r] = v;
    }
    __syncthreads();
    if (tid == 0) { arrive_cnt(&g_famc[ks]); arrive_cnt(&g_pairc[nt >> 1]); }

    // ldmatrix bases
    const uint32_t a_addr0 = sb + (uint32_t)((m*16 + (l & 7) + ((l >> 3) & 1) * 8) * RSTR
                                             + ((l >> 4) & 1) * 16);
    const uint32_t b_addr0 = sb + (uint32_t)((nh*16 + (l & 7) + ((l >> 4) & 1) * 8) * RSTR
                                             + ((l >> 3) & 1) * 16);

    // hoist ALL B fragments to registers (constant for all steps)
    uint32_t bh[8][4], bl[8][4];
    #pragma unroll
    for (int ss = 0; ss < 8; ss++) {
        ldsm4(bh[ss], b_addr0 + S_BHI + ss * 32);
        ldsm4(bl[ss], b_addr0 + S_BLO + ss * 32);
    }

    for (int s = 1; s <= NSTEP; s++) {
        // prefetch xin for this step's reduce
        const int t = (s + 1) >> 1;
        float xp = __ldcg(&g_xin[(size_t)t * BH + b_r * H_ + n_r]);

        // ---- wait h_{s-1} from family ks (tid0 polls, syncthreads broadcasts) ----
        if (tid == 0) wait_cnt(&g_famc[ks], (E + (unsigned)s) * 16u);
        __syncthreads();
        {
            const __nv_bfloat16* hsrc_h = g_hh[(s-1) & 1];
            const __nv_bfloat16* hsrc_l = g_hl[(s-1) & 1];
            #pragma unroll
            for (int it = 0; it < 4; it++) {
                int f = tid + it * 512;              // 2048: buf(2) x row(64) x q(16)
                int buf = f >> 10, g = f & 1023;
                int row = g >> 4, q = g & 15;
                const __nv_bfloat16* src = (buf ? hsrc_l : hsrc_h) + row * H_ + ks*128 + q*8;
                char* dst = smem + (buf ? S_ALO : S_AHI) + row * RSTR + q * 16;
                *(uint4*)dst = __ldcg((const uint4*)src);
            }
        }
        __syncthreads();

        // ---- GEMM: split accumulator chains (hh 8-deep; mixed 16-deep) ----
        float dhh[2][4] = {}, dml[2][4] = {};
        #pragma unroll
        for (int ss = 0; ss < 8; ss++) {
            uint32_t a_hi[4], a_lo[4];
            ldsm4(a_hi, a_addr0 + S_AHI + ss * 32);
            ldsm4(a_lo, a_addr0 + S_ALO + ss * 32);
            mma_bf16(dhh[0], a_hi, bh[ss] + 0);
            mma_bf16(dhh[1], a_hi, bh[ss] + 2);
            mma_bf16(dml[0], a_hi, bl[ss] + 0);
            mma_bf16(dml[1], a_hi, bl[ss] + 2);
            mma_bf16(dml[0], a_lo, bh[ss] + 0);
            mma_bf16(dml[1], a_lo, bh[ss] + 2);
        }
        {
            float* pb = g_part2[s & 1];
            int row0 = m*16 + (l >> 2);
            int gcol = nt*64 + nh*16 + (l & 3) * 2;
            float* p = &pb[ks*BH + row0*H_ + gcol];
            #pragma unroll
            for (int ns = 0; ns < 2; ns++) {
                *(float2*)(p + ns*8) =
                    make_float2(dhh[ns][0] + dml[ns][0], dhh[ns][1] + dml[ns][1]);
                *(float2*)(p + ns*8 + 8*H_) =
                    make_float2(dhh[ns][2] + dml[ns][2], dhh[ns][3] + dml[ns][3]);
            }
        }
        __syncthreads();
        if (tid == 0) arrive_cnt(&g_pairc[nt >> 1]);

        // ---- wait parts from nts {2ks,2ks+1}, reduce own chunk ----
        if (tid == 0) wait_cnt(&g_pairc[ks], (E + (unsigned)s + 1u) * 16u);
        __syncthreads();
        {
            const float* pb = g_part2[s & 1];
            float acc = xp;
            #pragma unroll
            for (int p = 0; p < 8; p++)
                acc += __ldcg(&pb[p*BH + b_r*H_ + n_r]);
            float v = tanhf(acc);
            __nv_bfloat16 hi, lo;
            split_bf16(v, hi, lo);
            g_hh[s & 1][b_r * H_ + n_r] = hi;
            g_hl[s & 1][b_r * H_ + n_r] = lo;
            __syncthreads();
            if (tid == 0) arrive_cnt(&g_famc[ks]);
            if ((s & 1) == 0)    // off the critical path
                out_hist[(size_t)b_r * (T_*H_) + t * H_ + n_r] = v;
        }
    }
    if (bx == 0 && tid == 0) g_epoch = E + (unsigned)(NSTEP + 1);
}

// ================= Kernel 3: fc — fc_w converted inline (no prepass) ==========
#define FSTR 144
#define FA_HI 0
#define FA_LO (64*FSTR)
#define FB_HI (2*64*FSTR)
#define FB_LO (FB_HI + 256*FSTR)
#define FS_TOTAL (FB_LO + 256*FSTR)
__global__ void __launch_bounds__(256, 1)
fc_mma_kernel(const float* __restrict__ fc_w, const float* __restrict__ fc_b,
              float* __restrict__ y) {
    extern __shared__ __align__(16) char smem[];
    const uint32_t sb = smem_u32(smem);
    const int tid = threadIdx.x;
    const int wid = tid >> 5, l = tid & 31;
    const int mw = wid & 1, nw = wid >> 1;
    const int c0 = blockIdx.x * 256;

    const uint32_t a_off = (uint32_t)((mw*32 + (l & 7) + ((l >> 3) & 1) * 8) * FSTR
                                      + ((l >> 4) & 1) * 16);
    const uint32_t b_off = (uint32_t)((nw*64 + (l & 7) + ((l >> 4) & 1) * 8) * FSTR
                                      + ((l >> 3) & 1) * 16);

    float d[2][8][4] = {};
    for (int kc = 0; kc < 16; kc++) {
        __syncthreads();
        // stage A: 64x64 hi+lo from g_hh/g_hl[0]
        #pragma unroll
        for (int it = 0; it < 4; it++) {
            int f = tid + it * 256;
            int buf = f >> 9, g = f & 511;
            int row = g >> 3, q = g & 7;
            const __nv_bfloat16* src = (buf ? g_hl[0] : g_hh[0]) + row * H_ + kc*64 + q*8;
            *(uint4*)(smem + (buf ? FA_LO : FA_HI) + row*FSTR + q*16) = *(const uint4*)src;
        }
        // stage B: 256 rows x 64 k from fp32 fc_w, split inline
        #pragma unroll
        for (int it = 0; it < 16; it++) {
            int f = tid + it * 256;            // 4096 float4 tasks: row(256) x q4(16)
            int row = f >> 4, q4 = f & 15;
            float4 v = *(const float4*)&fc_w[(size_t)(c0 + row) * H_ + kc*64 + q4*4];
            __nv_bfloat16 hx, lx, hy, ly, hz, lz, hw, lw;
            split_bf16(v.x, hx, lx); split_bf16(v.y, hy, ly);
            split_bf16(v.z, hz, lz); split_bf16(v.w, hw, lw);
            uint32_t ho = (uint32_t)(row*FSTR + q4*8);
            *(__nv_bfloat162*)(smem + FB_HI + ho)     = __halves2bfloat162(hx, hy);
            *(__nv_bfloat162*)(smem + FB_HI + ho + 4) = __halves2bfloat162(hz, hw);
            *(__nv_bfloat162*)(smem + FB_LO + ho)     = __halves2bfloat162(lx, ly);
            *(__nv_bfloat162*)(smem + FB_LO + ho + 4) = __halves2bfloat162(lz, lw);
        }
        __syncthreads();
        #pragma unroll
        for (int s = 0; s < 4; s++) {
            uint32_t ahi[2][4], alo[2][4];
            #pragma unroll
            for (int i = 0; i < 2; i++) {
                uint32_t ao = a_off + (uint32_t)(i * 16 * FSTR) + s * 32;
                ldsm4(ahi[i], sb + FA_HI + ao);
                ldsm4(alo[i], sb + FA_LO + ao);
            }
            #pragma unroll
            for (int np = 0; np < 4; np++) {
                uint32_t bhi[4], blo[4];
                uint32_t bo = b_off + (uint32_t)(np * 16 * FSTR) + s * 32;
                ldsm4(bhi, sb + FB_HI + bo);
                ldsm4(blo, sb + FB_LO + bo);
                #pragma unroll
                for (int h = 0; h < 2; h++) {
                    int ns = np*2 + h;
                    #pragma unroll
                    for (int i = 0; i < 2; i++) {
                        mma_bf16(d[i][ns], ahi[i], bhi + h*2);
                        mma_bf16(d[i][ns], ahi[i], blo + h*2);
                        mma_bf16(d[i][ns], alo[i], bhi + h*2);
                    }
                }
            }
        }
    }
    #pragma unroll
    for (int i = 0; i < 2; i++) {
        int row = mw*32 + i*16 + (l >> 2);
        #pragma unroll
        for (int ns = 0; ns < 8; ns++) {
            int col = c0 + nw*64 + ns*8 + (l & 3) * 2;
            float2 bb = *(const float2*)&fc_b[col];
            *(float2*)&y[(size_t)row * C_ + col] =
                make_float2(d[i][ns][0] + bb.x, d[i][ns][1] + bb.y);
            *(float2*)&y[(size_t)(row + 8) * C_ + col] =
                make_float2(d[i][ns][2] + bb.x, d[i][ns][3] + bb.y);
        }
    }
}

// ================= launch =================
extern "C" void kernel_launch(void* const* d_in, const int* in_sizes, int n_in,
                              void* d_out, int out_size) {
    const int*   x    = (const int*)  d_in[0];
    const float* emb  = (const float*)d_in[1];
    const float* w1   = (const float*)d_in[2];
    const float* b1   = (const float*)d_in[3];
    const float* fc_w = (const float*)d_in[4];
    const float* fc_b = (const float*)d_in[5];
    float* out = (float*)d_out;

    conv_wx_kernel<<<H_, 256>>>(w1);
    conv_xe_kernel<<<M_/8, 256>>>(x, emb);

    dim3 gx(H_/128, M_/128);
    cudaFuncSetAttribute(xin_mma_kernel, cudaFuncAttributeMaxDynamicSharedMemorySize, XS_TOTAL);
    xin_mma_kernel<<<gx, 256, XS_TOTAL>>>(b1);

    cudaFuncSetAttribute(recur_kernel, cudaFuncAttributeMaxDynamicSharedMemorySize, S_TOTAL);
    recur_kernel<<<GRID_G, 512, S_TOTAL>>>(w1, out + YSIZE);

    cudaFuncSetAttribute(fc_mma_kernel, cudaFuncAttributeMaxDynamicSharedMemorySize, FS_TOTAL);
    fc_mma_kernel<<<C_/256, 256, FS_TOTAL>>>(fc_w, fc_b, out);
}

// round 16
// speedup vs baseline: 1.6839x; 1.1978x over previous
#include <cuda_runtime.h>
#include <cuda_bf16.h>
#include <math.h>
#include <stdint.h>

// Problem constants
#define T_    512
#define B_    64
#define H_    1024
#define C_    32000
#define SIXH  6144
#define M_    (T_*B_)
#define BH    (B_*H_)
#define YSIZE (B_*C_)
#define GRID_G 128
#define NSTEP 1022

// -------- scratch --------
__device__ float    g_xin[M_*H_];
__device__ __nv_bfloat16 g_hh[2][BH];
__device__ __nv_bfloat16 g_hl[2][BH];
__device__ __nv_bfloat16 g_xe_hi[M_*H_];
__device__ __nv_bfloat16 g_xe_lo[M_*H_];
__device__ __nv_bfloat16 g_wx_hi[H_*H_];
__device__ __nv_bfloat16 g_wx_lo[H_*H_];
__device__ unsigned g_qc[4];       // per-batch-quarter step counters (32 CTA arrivals/step)
__device__ unsigned g_epoch = 0;

__device__ __forceinline__ void arrive_cnt(unsigned* c) {
    asm volatile("red.release.gpu.global.add.u32 [%0], %1;" :: "l"(c), "r"(1u) : "memory");
}
__device__ __forceinline__ void wait_cnt(unsigned* c, unsigned target) {
    unsigned v;
    do { asm volatile("ld.acquire.gpu.global.u32 %0, [%1];" : "=r"(v) : "l"(c) : "memory"); }
    while (v < target);
}

__device__ __forceinline__ uint32_t smem_u32(const void* p) {
    uint32_t a;
    asm("{ .reg .u64 t; cvta.to.shared.u64 t, %1; cvt.u32.u64 %0, t; }" : "=r"(a) : "l"(p));
    return a;
}
__device__ __forceinline__ void ldsm4(uint32_t* r, uint32_t a) {
    asm volatile("ldmatrix.sync.aligned.m8n8.x4.shared.b16 {%0,%1,%2,%3}, [%4];"
        : "=r"(r[0]), "=r"(r[1]), "=r"(r[2]), "=r"(r[3]) : "r"(a));
}
__device__ __forceinline__ void mma_bf16(float* d, const uint32_t* a, const uint32_t* b) {
    asm volatile("mma.sync.aligned.m16n8k16.row.col.f32.bf16.bf16.f32 "
        "{%0,%1,%2,%3}, {%4,%5,%6,%7}, {%8,%9}, {%0,%1,%2,%3};"
        : "+f"(d[0]), "+f"(d[1]), "+f"(d[2]), "+f"(d[3])
        : "r"(a[0]), "r"(a[1]), "r"(a[2]), "r"(a[3]), "r"(b[0]), "r"(b[1]));
}
__device__ __forceinline__ void split_bf16(float v, __nv_bfloat16& hi, __nv_bfloat16& lo) {
    hi = __float2bfloat16(v);
    lo = __float2bfloat16(v - __bfloat162float(hi));
}

// ================= Prepass A: xe = emb[x] -> bf16 hi/lo =================
__global__ void conv_xe_kernel(const int* __restrict__ x, const float* __restrict__ emb) {
    const int tid = threadIdx.x;
    #pragma unroll
    for (int it = 0; it < 8; it++) {
        int r = blockIdx.x * 8 + it;
        int token = __ldg(&x[r]);
        float4 v = *(const float4*)&emb[(size_t)token * H_ + tid * 4];
        __nv_bfloat16 hx, lx, hy, ly, hz, lz, hw, lw;
        split_bf16(v.x, hx, lx); split_bf16(v.y, hy, ly);
        split_bf16(v.z, hz, lz); split_bf16(v.w, hw, lw);
        size_t o = (size_t)r * H_ + tid * 4;
        *(__nv_bfloat162*)&g_xe_hi[o]     = __halves2bfloat162(hx, hy);
        *(__nv_bfloat162*)&g_xe_hi[o + 2] = __halves2bfloat162(hz, hw);
        *(__nv_bfloat162*)&g_xe_lo[o]     = __halves2bfloat162(lx, ly);
        *(__nv_bfloat162*)&g_xe_lo[o + 2] = __halves2bfloat162(lz, lw);
    }
}

// ================= Prepass B: Wx -> bf16 hi/lo transposed [n][k] =================
__global__ void conv_wx_kernel(const float* __restrict__ w1) {
    const int n = blockIdx.x;
    for (int k = threadIdx.x; k < H_; k += 256) {
        float v = w1[(size_t)k * SIXH + n];
        __nv_bfloat16 hi, lo;
        split_bf16(v, hi, lo);
        g_wx_hi[n * H_ + k] = hi;
        g_wx_lo[n * H_ + k] = lo;
    }
}

// ================= Kernel 1: xin = xe @ Wx + b (round-13 proven, unchanged) ==========
#define XSTR 144
#define SA_HI 0
#define SA_LO (128*XSTR)
#define SB_HI (2*128*XSTR)
#define SB_LO (3*128*XSTR)
#define XS_TOTAL (4*128*XSTR)
__global__ void __launch_bounds__(256, 2)
xin_mma_kernel(const float* __restrict__ b1) {
    extern __shared__ __align__(16) char smem[];
    const uint32_t sb = smem_u32(smem);
    const int tid = threadIdx.x;
    const int wid = tid >> 5, l = tid & 31;
    const int mw = wid & 3, nw = wid >> 2;
    const int n0 = blockIdx.x * 128;
    const int r0 = blockIdx.y * 128;

    const uint32_t a_row = (uint32_t)(mw*32 + (l & 7) + ((l >> 3) & 1) * 8);
    const uint32_t a_off = a_row * XSTR + ((l >> 4) & 1) * 16;
    const uint32_t b_off = (uint32_t)((nw*64 + (l & 7) + ((l >> 4) & 1) * 8) * XSTR
                                      + ((l >> 3) & 1) * 16);

    float d[2][8][4] = {};
    for (int kc = 0; kc < 16; kc++) {
        __syncthreads();
        #pragma unroll
        for (int it = 0; it < 4; it++) {
            int f = tid + it * 256;
            int r = f >> 3, q = f & 7;
            size_t ga = (size_t)(r0 + r) * H_ + kc*64 + q*8;
            size_t gb = (size_t)(n0 + r) * H_ + kc*64 + q*8;
            *(uint4*)(smem + SA_HI + r*XSTR + q*16) = *(const uint4*)&g_xe_hi[ga];
            *(uint4*)(smem + SA_LO + r*XSTR + q*16) = *(const uint4*)&g_xe_lo[ga];
            *(uint4*)(smem + SB_HI + r*XSTR + q*16) = *(const uint4*)&g_wx_hi[gb];
            *(uint4*)(smem + SB_LO + r*XSTR + q*16) = *(const uint4*)&g_wx_lo[gb];
        }
        __syncthreads();
        #pragma unroll
        for (int s = 0; s < 4; s++) {
            uint32_t ahi[2][4], alo[2][4];
            #pragma unroll
            for (int i = 0; i < 2; i++) {
                uint32_t ao = a_off + (uint32_t)(i * 16 * XSTR) + s * 32;
                ldsm4(ahi[i], sb + SA_HI + ao);
                ldsm4(alo[i], sb + SA_LO + ao);
            }
            #pragma unroll
            for (int np = 0; np < 4; np++) {
                uint32_t bhi[4], blo[4];
                uint32_t bo = b_off + (uint32_t)(np * 16 * XSTR) + s * 32;
                ldsm4(bhi, sb + SB_HI + bo);
                ldsm4(blo, sb + SB_LO + bo);
                #pragma unroll
                for (int h = 0; h < 2; h++) {
                    int ns = np*2 + h;
                    #pragma unroll
                    for (int i = 0; i < 2; i++) {
                        mma_bf16(d[i][ns], ahi[i], bhi + h*2);
                        mma_bf16(d[i][ns], ahi[i], blo + h*2);
                        mma_bf16(d[i][ns], alo[i], bhi + h*2);
                    }
                }
            }
        }
    }
    #pragma unroll
    for (int i = 0; i < 2; i++) {
        int row = r0 + mw*32 + i*16 + (l >> 2);
        #pragma unroll
        for (int ns = 0; ns < 8; ns++) {
            int col = n0 + nw*64 + ns*8 + (l & 3) * 2;
            float2 bb = *(const float2*)&b1[col];
            *(float2*)&g_xin[(size_t)row * H_ + col] =
                make_float2(d[i][ns][0] + bb.x, d[i][ns][1] + bb.y);
            *(float2*)&g_xin[(size_t)(row + 8) * H_ + col] =
                make_float2(d[i][ns][2] + bb.x, d[i][ns][3] + bb.y);
        }
    }
}

// ================= Kernel 2: recurrence — batch-split, full-K, ONE handoff/step =======
// CTA (bq,nc): bq = bx>>5 (16 batch rows), nc = bx&31 (32 N cols).
// Warp (kg,nw): kg = wid>>2 (K group of 256), nw = wid&3 (8 N cols).
// Intra-CTA: 4 k-group partials reduced via smem (no global parts).
#define ASTR  2064                 // row stride bytes (1024 bf16 + 16 pad) — conflict-free
#define SB2_HI 0
#define SB2_LO (32*ASTR)           // 66048
#define SA2_HI (2*32*ASTR)         // 132096
#define SA2_LO (SA2_HI + 16*ASTR)  // 165120
#define SRED2  (SA2_LO + 16*ASTR)  // 198144 ; partials 4 x (16x34+..) words
#define S2_TOTAL (SRED2 + 4*544*4) // 206848 B

__global__ void __launch_bounds__(512, 1)
recur_kernel(const float* __restrict__ w1, float* __restrict__ out_hist) {
    extern __shared__ __align__(1024) char smem[];
    const uint32_t sb = smem_u32(smem);
    const int tid = threadIdx.x;
    const int wid = tid >> 5;
    const int l   = tid & 31;
    const int bx  = blockIdx.x;
    const int bq = bx >> 5, nc = bx & 31;
    const int kg = wid >> 2, nw = wid & 3;

    const unsigned E = __ldcg(&g_epoch);

    // one-time: Wh[k][32nc..+32] -> Bhi/Blo[n][k] bf16 in smem
    #pragma unroll
    for (int it = 0; it < 64; it++) {
        int f = tid + it * 512;               // 32768: k(1024) x n(32)
        int k = f >> 5, n = f & 31;
        float v = w1[(size_t)k * SIXH + H_ + nc*32 + n];
        __nv_bfloat16 hi, lo;
        split_bf16(v, hi, lo);
        *(__nv_bfloat16*)(smem + SB2_HI + n*ASTR + k*2) = hi;
        *(__nv_bfloat16*)(smem + SB2_LO + n*ASTR + k*2) = lo;
    }

    // output-chunk coords: 512 threads x 1 elem (16 rows x 32 cols)
    const int grow = bq*16 + (tid >> 5);
    const int gcol = nc*32 + (tid & 31);

    // prologue (s=0): h0 = tanh(xin[0])
    {
        float xv = g_xin[grow * H_ + gcol];
        float v = tanhf(xv);
        __nv_bfloat16 hi, lo;
        split_bf16(v, hi, lo);
        g_hh[0][grow * H_ + gcol] = hi;
        g_hl[0][grow * H_ + gcol] = lo;
        out_hist[(size_t)grow * (T_*H_) + gcol] = v;
    }
    __syncthreads();                       // h0 + B smem visible
    if (tid == 0) arrive_cnt(&g_qc[bq]);

    // hoist B fragments to regs: warp covers n8 rows [8nw..), K group [256kg..)
    uint32_t bh[16][2], bl[16][2];
    #pragma unroll
    for (int p = 0; p < 8; p++) {          // each x4 = 2 k-steps
        uint32_t addr = (uint32_t)((nw*8 + (l & 7)) * ASTR + kg*512 + p*64
                                   + ((l >> 3) & 3) * 16);
        uint32_t r[4];
        ldsm4(r, sb + SB2_HI + addr);
        bh[2*p][0] = r[0]; bh[2*p][1] = r[1]; bh[2*p+1][0] = r[2]; bh[2*p+1][1] = r[3];
        ldsm4(r, sb + SB2_LO + addr);
        bl[2*p][0] = r[0]; bl[2*p][1] = r[1]; bl[2*p+1][0] = r[2]; bl[2*p+1][1] = r[3];
    }

    // A ldmatrix bases (all warps share the 16 A rows)
    const uint32_t a_hi_base = sb + SA2_HI
        + (uint32_t)(((l & 7) + ((l >> 3) & 1) * 8) * ASTR + ((l >> 4) & 1) * 16);
    const uint32_t a_lo_base = a_hi_base + (uint32_t)(SA2_LO - SA2_HI);

    for (int s = 1; s <= NSTEP; s++) {
        const int t = (s + 1) >> 1;
        float xp = __ldcg(&g_xin[(size_t)t * BH + grow * H_ + gcol]);

        // ---- single handoff: wait own quarter's h(s-1) ----
        if (tid == 0) wait_cnt(&g_qc[bq], (E + (unsigned)s) * 32u);
        __syncthreads();                   // S1: fan-out

        // ---- stage A: 16 rows x 1024 k, hi+lo (8 uint4/thread) ----
        {
            const __nv_bfloat16* hh = g_hh[(s-1) & 1];
            const __nv_bfloat16* hl = g_hl[(s-1) & 1];
            #pragma unroll
            for (int it = 0; it < 8; it++) {
                int f = tid + it * 512;            // 4096: buf(2) x row(16) x q(128)
                int buf = f >> 11, g = f & 2047;
                int row = g >> 7, q = g & 127;
                const __nv_bfloat16* src = (buf ? hl : hh) + (bq*16 + row) * H_ + q*8;
                char* dst = smem + (buf ? SA2_LO : SA2_HI) + row * ASTR + q * 16;
                *(uint4*)dst = __ldcg((const uint4*)src);
            }
        }
        __syncthreads();                   // S2: stage -> GEMM

        // ---- GEMM: warp = m16 n8 k256 (48 mma), B in regs ----
        float dhh[4] = {}, dml[4] = {};
        #pragma unroll
        for (int ss = 0; ss < 16; ss++) {
            uint32_t a_hi[4], a_lo[4];
            uint32_t ko = (uint32_t)(kg*512 + ss*32);
            ldsm4(a_hi, a_hi_base + ko);
            ldsm4(a_lo, a_lo_base + ko);
            mma_bf16(dhh, a_hi, bh[ss]);
            mma_bf16(dml, a_hi, bl[ss]);
            mma_bf16(dml, a_lo, bh[ss]);
        }
        // store k-group partial to smem: partials[kg][16 rows (pad 34)][32 cols]
        {
            int r0w = (l >> 2), c0w = nw*8 + (l & 3)*2;
            float* pr = (float*)(smem + SRED2) + kg*544;
            *(float2*)(pr + r0w*34 + c0w)       = make_float2(dhh[0]+dml[0], dhh[1]+dml[1]);
            *(float2*)(pr + (r0w+8)*34 + c0w)   = make_float2(dhh[2]+dml[2], dhh[3]+dml[3]);
        }
        __syncthreads();                   // S3: partials -> reduce

        // ---- intra-CTA k-reduce + tanh + split + h store ----
        {
            const float* pr = (const float*)(smem + SRED2);
            int widx = (tid >> 5)*34 + (tid & 31);
            float acc = xp;
            #pragma unroll
            for (int k2 = 0; k2 < 4; k2++)
                acc += pr[k2*544 + widx];
            float v = tanhf(acc);
            __nv_bfloat16 hi, lo;
            split_bf16(v, hi, lo);
            g_hh[s & 1][grow * H_ + gcol] = hi;
            g_hl[s & 1][grow * H_ + gcol] = lo;
            __syncthreads();               // S4: h stores before arrive
            if (tid == 0) arrive_cnt(&g_qc[bq]);
            if ((s & 1) == 0)              // off the critical path
                out_hist[(size_t)grow * (T_*H_) + t * H_ + gcol] = v;
        }
    }
    if (bx == 0 && tid == 0) g_epoch = E + (unsigned)(NSTEP + 1);
}

// ================= Kernel 3: fc — fc_w converted inline (round-15 proven) ==========
#define FSTR 144
#define FA_HI 0
#define FA_LO (64*FSTR)
#define FB_HI (2*64*FSTR)
#define FB_LO (FB_HI + 256*FSTR)
#define FS_TOTAL (FB_LO + 256*FSTR)
__global__ void __launch_bounds__(256, 1)
fc_mma_kernel(const float* __restrict__ fc_w, const float* __restrict__ fc_b,
              float* __restrict__ y) {
    extern __shared__ __align__(16) char smem[];
    const uint32_t sb = smem_u32(smem);
    const int tid = threadIdx.x;
    const int wid = tid >> 5, l = tid & 31;
    const int mw = wid & 1, nw = wid >> 1;
    const int c0 = blockIdx.x * 256;

    const uint32_t a_off = (uint32_t)((mw*32 + (l & 7) + ((l >> 3) & 1) * 8) * FSTR
                                      + ((l >> 4) & 1) * 16);
    const uint32_t b_off = (uint32_t)((nw*64 + (l & 7) + ((l >> 4) & 1) * 8) * FSTR
                                      + ((l >> 3) & 1) * 16);

    float d[2][8][4] = {};
    for (int kc = 0; kc < 16; kc++) {
        __syncthreads();
        #pragma unroll
        for (int it = 0; it < 4; it++) {
            int f = tid + it * 256;
            int buf = f >> 9, g = f & 511;
            int row = g >> 3, q = g & 7;
            const __nv_bfloat16* src = (buf ? g_hl[0] : g_hh[0]) + row * H_ + kc*64 + q*8;
            *(uint4*)(smem + (buf ? FA_LO : FA_HI) + row*FSTR + q*16) = *(const uint4*)src;
        }
        #pragma unroll
        for (int it = 0; it < 16; it++) {
            int f = tid + it * 256;
            int row = f >> 4, q4 = f & 15;
            float4 v = *(const float4*)&fc_w[(size_t)(c0 + row) * H_ + kc*64 + q4*4];
            __nv_bfloat16 hx, lx, hy, ly, hz, lz, hw, lw;
            split_bf16(v.x, hx, lx); split_bf16(v.y, hy, ly);
            split_bf16(v.z, hz, lz); split_bf16(v.w, hw, lw);
            uint32_t ho = (uint32_t)(row*FSTR + q4*8);
            *(__nv_bfloat162*)(smem + FB_HI + ho)     = __halves2bfloat162(hx, hy);
            *(__nv_bfloat162*)(smem + FB_HI + ho + 4) = __halves2bfloat162(hz, hw);
            *(__nv_bfloat162*)(smem + FB_LO + ho)     = __halves2bfloat162(lx, ly);
            *(__nv_bfloat162*)(smem + FB_LO + ho + 4) = __halves2bfloat162(lz, lw);
        }
        __syncthreads();
        #pragma unroll
        for (int s = 0; s < 4; s++) {
            uint32_t ahi[2][4], alo[2][4];
            #pragma unroll
            for (int i = 0; i < 2; i++) {
                uint32_t ao = a_off + (uint32_t)(i * 16 * FSTR) + s * 32;
                ldsm4(ahi[i], sb + FA_HI + ao);
                ldsm4(alo[i], sb + FA_LO + ao);
            }
            #pragma unroll
            for (int np = 0; np < 4; np++) {
                uint32_t bhi[4], blo[4];
                uint32_t bo = b_off + (uint32_t)(np * 16 * FSTR) + s * 32;
                ldsm4(bhi, sb + FB_HI + bo);
                ldsm4(blo, sb + FB_LO + bo);
                #pragma unroll
                for (int h = 0; h < 2; h++) {
                    int ns = np*2 + h;
                    #pragma unroll
                    for (int i = 0; i < 2; i++) {
                        mma_bf16(d[i][ns], ahi[i], bhi + h*2);
                        mma_bf16(d[i][ns], ahi[i], blo + h*2);
                        mma_bf16(d[i][ns], alo[i], bhi + h*2);
                    }
                }
            }
        }
    }
    #pragma unroll
    for (int i = 0; i < 2; i++) {
        int row = mw*32 + i*16 + (l >> 2);
        #pragma unroll
        for (int ns = 0; ns < 8; ns++) {
            int col = c0 + nw*64 + ns*8 + (l & 3) * 2;
            float2 bb = *(const float2*)&fc_b[col];
            *(float2*)&y[(size_t)row * C_ + col] =
                make_float2(d[i][ns][0] + bb.x, d[i][ns][1] + bb.y);
            *(float2*)&y[(size_t)(row + 8) * C_ + col] =
                make_float2(d[i][ns][2] + bb.x, d[i][ns][3] + bb.y);
        }
    }
}

// ================= launch =================
extern "C" void kernel_launch(void* const* d_in, const int* in_sizes, int n_in,
                              void* d_out, int out_size) {
    const int*   x    = (const int*)  d_in[0];
    const float* emb  = (const float*)d_in[1];
    const float* w1   = (const float*)d_in[2];
    const float* b1   = (const float*)d_in[3];
    const float* fc_w = (const float*)d_in[4];
    const float* fc_b = (const float*)d_in[5];
    float* out = (float*)d_out;

    conv_wx_kernel<<<H_, 256>>>(w1);
    conv_xe_kernel<<<M_/8, 256>>>(x, emb);

    dim3 gx(H_/128, M_/128);
    cudaFuncSetAttribute(xin_mma_kernel, cudaFuncAttributeMaxDynamicSharedMemorySize, XS_TOTAL);
    xin_mma_kernel<<<gx, 256, XS_TOTAL>>>(b1);

    cudaFuncSetAttribute(recur_kernel, cudaFuncAttributeMaxDynamicSharedMemorySize, S2_TOTAL);
    recur_kernel<<<GRID_G, 512, S2_TOTAL>>>(w1, out + YSIZE);

    cudaFuncSetAttribute(fc_mma_kernel, cudaFuncAttributeMaxDynamicSharedMemorySize, FS_TOTAL);
    fc_mma_kernel<<<C_/256, 256, FS_TOTAL>>>(fc_w, fc_b, out);
}